// round 1
// baseline (speedup 1.0000x reference)
#include <cuda_runtime.h>
#include <cuda_bf16.h>

#define D        64
#define MAXN     100032           // padded
#define PITCH    68               // smem row pitch (floats), multiple of 4 for LDS.128

// Static device scratch (no allocations allowed).
__device__ float g_agg[(size_t)MAXN * D];   // scatter-add accumulator (both layers)
__device__ float g_deg[MAXN];               // in-degree (computed once)
__device__ float g_h[(size_t)MAXN * D];     // layer-1 output

// ---------------------------------------------------------------------------
// Zero kernel: zeroes agg (as float4) plus one extra buffer (deg or d_out).
// ---------------------------------------------------------------------------
__global__ __launch_bounds__(256) void zero_kernel(int n_agg4, int n_extra4, float4* extra) {
    int i = blockIdx.x * 256 + threadIdx.x;
    float4 z = make_float4(0.f, 0.f, 0.f, 0.f);
    if (i < n_agg4) {
        reinterpret_cast<float4*>(g_agg)[i] = z;
    } else {
        i -= n_agg4;
        if (i < n_extra4) extra[i] = z;
    }
}

// ---------------------------------------------------------------------------
// Edge scatter: 16 threads per edge, one float4 atomicAdd each (64 floats).
// Optionally accumulates degree (layer 1 only).
// ---------------------------------------------------------------------------
__global__ __launch_bounds__(256) void scatter_kernel(const float* __restrict__ feat,
                                                      const int* __restrict__ src,
                                                      const int* __restrict__ dst,
                                                      int E, int with_deg) {
    int idx = blockIdx.x * 256 + threadIdx.x;
    int e = idx >> 4;
    if (e >= E) return;
    int t = idx & 15;
    int s = __ldg(src + e);
    int d = __ldg(dst + e);
    float4 v = __ldg(reinterpret_cast<const float4*>(feat) + (size_t)s * 16 + t);
    atomicAdd(reinterpret_cast<float4*>(g_agg) + (size_t)d * 16 + t, v);
    if (with_deg && t == 0) atomicAdd(&g_deg[d], 1.0f);
}

// ---------------------------------------------------------------------------
// Fused SAGE layer: out = act( (agg/deg) @ Wl^T + b + x @ Wr^T )
//   do_pool=0 : act = relu, write to hout
//   do_pool=1 : no relu, segmented block-local pool into pool_out (atomics)
// Tile: 64 nodes x 64 outs per block, 256 threads, 4x4 register micro-tiles.
// Smem: mean^T[k][n], x^T[k][n], Wl^T[k][j], Wr^T[k][j]  (pitch 68)
// ---------------------------------------------------------------------------
__global__ __launch_bounds__(256) void sage_kernel(const float* __restrict__ xin,
                                                   const float* __restrict__ Wl,
                                                   const float* __restrict__ bl,
                                                   const float* __restrict__ Wr,
                                                   float* __restrict__ hout,
                                                   const int* __restrict__ batch,
                                                   float* __restrict__ pool_out,
                                                   int N, int do_pool) {
    extern __shared__ float sm[];
    float* sM    = sm;                    // 64*PITCH
    float* sX    = sm + 64 * PITCH;
    float* sWl   = sm + 2 * 64 * PITCH;
    float* sWr   = sm + 3 * 64 * PITCH;
    float* sRdeg = sm + 4 * 64 * PITCH;   // 64
    int*   sBat  = reinterpret_cast<int*>(sRdeg + 64); // 64

    const int tid  = threadIdx.x;
    const int base = blockIdx.x * 64;

    if (tid < 64) {
        int node = base + tid;
        float dg = (node < N) ? g_deg[node] : 1.0f;
        sRdeg[tid] = 1.0f / fmaxf(dg, 1.0f);
        sBat[tid]  = (do_pool && node < N) ? __ldg(&batch[node]) : 0;
    }
    __syncthreads();

    // Cooperative transposed loads.
    for (int i = tid; i < 4096; i += 256) {
        int n = i >> 6, k = i & 63;
        int node = base + n;
        float m = 0.f, xv = 0.f;
        if (node < N) {
            m  = g_agg[(size_t)node * 64 + k] * sRdeg[n];
            xv = __ldg(&xin[(size_t)node * 64 + k]);
        }
        sM[k * PITCH + n] = m;
        sX[k * PITCH + n] = xv;
        // W is [j][k] row-major; store transposed [k][j] (j == n index here).
        sWl[k * PITCH + n] = __ldg(&Wl[i]);
        sWr[k * PITCH + n] = __ldg(&Wr[i]);
    }
    __syncthreads();

    const int n0 = (tid & 15) * 4;
    const int j0 = (tid >> 4) * 4;

    float acc[4][4];
#pragma unroll
    for (int a = 0; a < 4; a++)
#pragma unroll
        for (int b = 0; b < 4; b++) acc[a][b] = 0.f;

#pragma unroll 8
    for (int k = 0; k < 64; ++k) {
        const float4 am = *reinterpret_cast<const float4*>(&sM[k * PITCH + n0]);
        const float4 ax = *reinterpret_cast<const float4*>(&sX[k * PITCH + n0]);
        const float4 wl = *reinterpret_cast<const float4*>(&sWl[k * PITCH + j0]);
        const float4 wr = *reinterpret_cast<const float4*>(&sWr[k * PITCH + j0]);
        const float amv[4] = {am.x, am.y, am.z, am.w};
        const float axv[4] = {ax.x, ax.y, ax.z, ax.w};
        const float wlv[4] = {wl.x, wl.y, wl.z, wl.w};
        const float wrv[4] = {wr.x, wr.y, wr.z, wr.w};
#pragma unroll
        for (int ni = 0; ni < 4; ni++)
#pragma unroll
            for (int ji = 0; ji < 4; ji++)
                acc[ni][ji] += amv[ni] * wlv[ji] + axv[ni] * wrv[ji];
    }

    const float bv0 = __ldg(&bl[j0 + 0]);
    const float bv1 = __ldg(&bl[j0 + 1]);
    const float bv2 = __ldg(&bl[j0 + 2]);
    const float bv3 = __ldg(&bl[j0 + 3]);

    if (!do_pool) {
#pragma unroll
        for (int ni = 0; ni < 4; ni++) {
            int node = base + n0 + ni;
            if (node < N) {
                float4 v;
                v.x = fmaxf(acc[ni][0] + bv0, 0.f);
                v.y = fmaxf(acc[ni][1] + bv1, 0.f);
                v.z = fmaxf(acc[ni][2] + bv2, 0.f);
                v.w = fmaxf(acc[ni][3] + bv3, 0.f);
                *reinterpret_cast<float4*>(&hout[(size_t)node * 64 + j0]) = v;
            }
        }
    } else {
        __syncthreads();  // done reading sM; reuse it as [n][j] tile
#pragma unroll
        for (int ni = 0; ni < 4; ni++) {
            int n = n0 + ni;
            int node = base + n;
            float4 v;
            if (node < N) {
                v.x = acc[ni][0] + bv0;
                v.y = acc[ni][1] + bv1;
                v.z = acc[ni][2] + bv2;
                v.w = acc[ni][3] + bv3;
            } else {
                v = make_float4(0.f, 0.f, 0.f, 0.f);
            }
            *reinterpret_cast<float4*>(&sM[n * PITCH + j0]) = v;
        }
        __syncthreads();
        if (tid < 64) {
            const int j = tid;
            int cur = sBat[0];
            float sum = 0.f;
#pragma unroll 4
            for (int n = 0; n < 64; n++) {
                int b = sBat[n];
                if (b != cur) {
                    atomicAdd(&pool_out[cur * 64 + j], sum);
                    sum = 0.f;
                    cur = b;
                }
                sum += sM[n * PITCH + j];
            }
            atomicAdd(&pool_out[cur * 64 + j], sum);
        }
    }
}

// ---------------------------------------------------------------------------
// Finalize: counts via binary search on sorted batch, divide pooled sums.
// ---------------------------------------------------------------------------
__global__ __launch_bounds__(256) void finalize_kernel(float* __restrict__ out,
                                                       const int* __restrict__ batch,
                                                       int N) {
    __shared__ int s_cnt[64];
    int tid = threadIdx.x;
    if (tid < 64) {
        int lo0 = 0, hi = N;
        // lower_bound(tid)
        while (lo0 < hi) { int mid = (lo0 + hi) >> 1; if (__ldg(&batch[mid]) < tid) lo0 = mid + 1; else hi = mid; }
        int lo1 = lo0; hi = N;
        // lower_bound(tid+1)
        while (lo1 < hi) { int mid = (lo1 + hi) >> 1; if (__ldg(&batch[mid]) < tid + 1) lo1 = mid + 1; else hi = mid; }
        s_cnt[tid] = lo1 - lo0;
    }
    __syncthreads();
    for (int i = tid; i < 64 * 64; i += 256) {
        float c = (float)s_cnt[i >> 6];
        out[i] = out[i] / fmaxf(c, 1.0f);
    }
}

// ---------------------------------------------------------------------------
// kernel_launch
// Inputs (metadata order): x, edge_index, edge_attr, batch, edge_emb,
//                          W1_l, b1_l, W1_r, W2_l, b2_l, W2_r
// ---------------------------------------------------------------------------
extern "C" void kernel_launch(void* const* d_in, const int* in_sizes, int n_in,
                              void* d_out, int out_size) {
    const float* x     = (const float*)d_in[0];
    const int*   eidx  = (const int*)d_in[1];
    const int*   batch = (const int*)d_in[3];
    const float* W1l   = (const float*)d_in[5];
    const float* b1l   = (const float*)d_in[6];
    const float* W1r   = (const float*)d_in[7];
    const float* W2l   = (const float*)d_in[8];
    const float* b2l   = (const float*)d_in[9];
    const float* W2r   = (const float*)d_in[10];
    float*       out   = (float*)d_out;

    const int N = in_sizes[3];
    const int E = in_sizes[1] / 2;
    const int* src = eidx;
    const int* dst = eidx + E;

    void* hp = nullptr;  void* degp = nullptr;
    cudaGetSymbolAddress(&hp,   g_h);
    cudaGetSymbolAddress(&degp, g_deg);
    float* hptr   = (float*)hp;
    float* degptr = (float*)degp;

    const int smem = (4 * 64 * PITCH + 64) * (int)sizeof(float) + 64 * (int)sizeof(int);
    cudaFuncSetAttribute(sage_kernel, cudaFuncAttributeMaxDynamicSharedMemorySize, smem);

    const int n_agg4  = N * 16;            // N*64 floats as float4
    const int deg4    = (N + 3) / 4;
    const int out4    = out_size / 4;      // 4096/4
    const int zb0     = (n_agg4 + deg4 + 255) / 256;
    const int zb1     = (n_agg4 + out4 + 255) / 256;
    const int sblocks = (E * 16 + 255) / 256;
    const int gblocks = (N + 63) / 64;

    // Layer 1
    zero_kernel<<<zb0, 256>>>(n_agg4, deg4, reinterpret_cast<float4*>(degptr));
    scatter_kernel<<<sblocks, 256>>>(x, src, dst, E, 1);
    sage_kernel<<<gblocks, 256, smem>>>(x, W1l, b1l, W1r, hptr, nullptr, nullptr, N, 0);

    // Layer 2 + pool
    zero_kernel<<<zb1, 256>>>(n_agg4, out4, reinterpret_cast<float4*>(out));
    scatter_kernel<<<sblocks, 256>>>(hptr, src, dst, E, 0);
    sage_kernel<<<gblocks, 256, smem>>>(hptr, W2l, b2l, W2r, nullptr, batch, out, N, 1);

    finalize_kernel<<<1, 256>>>(out, batch, N);
}

// round 2
// speedup vs baseline: 1.1988x; 1.1988x over previous
#include <cuda_runtime.h>
#include <cuda_bf16.h>

#define D        64
#define MAXN     100352           // padded to multiple of 1024 (scan chunks)
#define MAXE     1000000
#define PITCH    68               // smem row pitch (floats), multiple of 4 for LDS.128
#define CHUNK    1024

// Static device scratch (no allocations allowed).
__device__ float g_agg[(size_t)MAXN * D];   // aggregation result (both layers)
__device__ float g_h[(size_t)MAXN * D];     // layer-1 output
__device__ int   g_cnt[MAXN];               // in-degree histogram (padded, zeroed)
__device__ int   g_off[MAXN];               // exclusive-scan offsets
__device__ int   g_cursor[MAXN];            // fill cursors
__device__ int   g_srcs[MAXE];              // src node per dst-sorted edge
__device__ int   g_chunksum[128];           // per-chunk totals
__device__ int   g_chunkbase[128];          // scanned chunk bases

// ---------------------------------------------------------------------------
// k0: zero histogram (padded), cursors, and the pooled output.
// ---------------------------------------------------------------------------
__global__ __launch_bounds__(256) void zero_kernel(int n_pad, int n_cur,
                                                   float* __restrict__ out, int n_out) {
    int i = blockIdx.x * 256 + threadIdx.x;
    if (i < n_pad) g_cnt[i] = 0;
    if (i < n_cur) g_cursor[i] = 0;
    if (i < n_out) out[i] = 0.f;
}

// ---------------------------------------------------------------------------
// k1: in-degree histogram over dst.
// ---------------------------------------------------------------------------
__global__ __launch_bounds__(256) void hist_kernel(const int* __restrict__ dst, int E) {
    int e = blockIdx.x * 256 + threadIdx.x;
    if (e < E) atomicAdd(&g_cnt[__ldg(&dst[e])], 1);
}

// ---------------------------------------------------------------------------
// k2: per-chunk (1024) exclusive scan of g_cnt -> g_off, chunk total -> g_chunksum.
// ---------------------------------------------------------------------------
__global__ __launch_bounds__(256) void scan_chunk_kernel() {
    __shared__ int w[256];
    int t = threadIdx.x;
    int base = blockIdx.x * CHUNK + t * 4;
    int4 c = *reinterpret_cast<const int4*>(&g_cnt[base]);
    int s0 = c.x, s1 = s0 + c.y, s2 = s1 + c.z, s3 = s2 + c.w;
    w[t] = s3;
    __syncthreads();
#pragma unroll
    for (int off = 1; off < 256; off <<= 1) {
        int v = (t >= off) ? w[t - off] : 0;
        __syncthreads();
        w[t] += v;
        __syncthreads();
    }
    int excl = (t > 0) ? w[t - 1] : 0;
    int4 o;
    o.x = excl; o.y = excl + s0; o.z = excl + s1; o.w = excl + s2;
    *reinterpret_cast<int4*>(&g_off[base]) = o;
    if (t == 255) g_chunksum[blockIdx.x] = w[255];
}

// ---------------------------------------------------------------------------
// k3: exclusive scan of chunk totals (<=128) -> g_chunkbase. One block.
// ---------------------------------------------------------------------------
__global__ __launch_bounds__(128) void scan_tops_kernel(int nchunk) {
    __shared__ int s[128];
    int t = threadIdx.x;
    s[t] = (t < nchunk) ? g_chunksum[t] : 0;
    __syncthreads();
#pragma unroll
    for (int off = 1; off < 128; off <<= 1) {
        int v = (t >= off) ? s[t - off] : 0;
        __syncthreads();
        s[t] += v;
        __syncthreads();
    }
    g_chunkbase[t] = (t > 0) ? s[t - 1] : 0;
}

// ---------------------------------------------------------------------------
// k4: add chunk bases.
// ---------------------------------------------------------------------------
__global__ __launch_bounds__(256) void add_base_kernel(int n_pad) {
    int i = blockIdx.x * 256 + threadIdx.x;
    if (i < n_pad) g_off[i] += g_chunkbase[i >> 10];
}

// ---------------------------------------------------------------------------
// k5: fill dst-sorted src list.
// ---------------------------------------------------------------------------
__global__ __launch_bounds__(256) void fill_kernel(const int* __restrict__ src,
                                                   const int* __restrict__ dst, int E) {
    int e = blockIdx.x * 256 + threadIdx.x;
    if (e >= E) return;
    int d = __ldg(&dst[e]);
    int p = atomicAdd(&g_cursor[d], 1);
    g_srcs[g_off[d] + p] = __ldg(&src[e]);
}

// ---------------------------------------------------------------------------
// Gather aggregation: 16 threads per dst node, float4 lanes, unroll-2 over edges.
// Writes sums non-atomically (full overwrite -> no zeroing needed).
// ---------------------------------------------------------------------------
__global__ __launch_bounds__(256) void agg_kernel(const float* __restrict__ feat, int N) {
    int g = blockIdx.x * 16 + (threadIdx.x >> 4);
    if (g >= N) return;
    int lane = threadIdx.x & 15;
    int start = g_off[g];
    int cnt   = g_cnt[g];
    const float4* f4 = reinterpret_cast<const float4*>(feat);
    float4 a0 = make_float4(0.f, 0.f, 0.f, 0.f);
    float4 a1 = make_float4(0.f, 0.f, 0.f, 0.f);
    int i = 0;
    for (; i + 2 <= cnt; i += 2) {
        int s0 = __ldg(&g_srcs[start + i]);
        int s1 = __ldg(&g_srcs[start + i + 1]);
        float4 v0 = __ldg(f4 + (size_t)s0 * 16 + lane);
        float4 v1 = __ldg(f4 + (size_t)s1 * 16 + lane);
        a0.x += v0.x; a0.y += v0.y; a0.z += v0.z; a0.w += v0.w;
        a1.x += v1.x; a1.y += v1.y; a1.z += v1.z; a1.w += v1.w;
    }
    if (i < cnt) {
        int s0 = __ldg(&g_srcs[start + i]);
        float4 v0 = __ldg(f4 + (size_t)s0 * 16 + lane);
        a0.x += v0.x; a0.y += v0.y; a0.z += v0.z; a0.w += v0.w;
    }
    a0.x += a1.x; a0.y += a1.y; a0.z += a1.z; a0.w += a1.w;
    reinterpret_cast<float4*>(g_agg)[(size_t)g * 16 + lane] = a0;
}

// ---------------------------------------------------------------------------
// Fused SAGE layer: out = act( (agg/deg) @ Wl^T + b + x @ Wr^T )
//   do_pool=0 : act = relu, write to hout
//   do_pool=1 : no relu, segmented block-local pool into pool_out (atomics)
// Tile: 64 nodes x 64 outs per block, 256 threads, 4x4 register micro-tiles.
// ---------------------------------------------------------------------------
__global__ __launch_bounds__(256) void sage_kernel(const float* __restrict__ xin,
                                                   const float* __restrict__ Wl,
                                                   const float* __restrict__ bl,
                                                   const float* __restrict__ Wr,
                                                   float* __restrict__ hout,
                                                   const int* __restrict__ batch,
                                                   float* __restrict__ pool_out,
                                                   int N, int do_pool) {
    extern __shared__ float sm[];
    float* sM    = sm;                    // 64*PITCH
    float* sX    = sm + 64 * PITCH;
    float* sWl   = sm + 2 * 64 * PITCH;
    float* sWr   = sm + 3 * 64 * PITCH;
    float* sRdeg = sm + 4 * 64 * PITCH;   // 64
    int*   sBat  = reinterpret_cast<int*>(sRdeg + 64); // 64

    const int tid  = threadIdx.x;
    const int base = blockIdx.x * 64;

    if (tid < 64) {
        int node = base + tid;
        float dg = (node < N) ? (float)g_cnt[node] : 1.0f;
        sRdeg[tid] = 1.0f / fmaxf(dg, 1.0f);
        sBat[tid]  = (do_pool && node < N) ? __ldg(&batch[node]) : 0;
    }
    __syncthreads();

    // Cooperative transposed loads.
    for (int i = tid; i < 4096; i += 256) {
        int n = i >> 6, k = i & 63;
        int node = base + n;
        float m = 0.f, xv = 0.f;
        if (node < N) {
            m  = g_agg[(size_t)node * 64 + k] * sRdeg[n];
            xv = __ldg(&xin[(size_t)node * 64 + k]);
        }
        sM[k * PITCH + n] = m;
        sX[k * PITCH + n] = xv;
        sWl[k * PITCH + n] = __ldg(&Wl[i]);
        sWr[k * PITCH + n] = __ldg(&Wr[i]);
    }
    __syncthreads();

    const int n0 = (tid & 15) * 4;
    const int j0 = (tid >> 4) * 4;

    float acc[4][4];
#pragma unroll
    for (int a = 0; a < 4; a++)
#pragma unroll
        for (int b = 0; b < 4; b++) acc[a][b] = 0.f;

#pragma unroll 8
    for (int k = 0; k < 64; ++k) {
        const float4 am = *reinterpret_cast<const float4*>(&sM[k * PITCH + n0]);
        const float4 ax = *reinterpret_cast<const float4*>(&sX[k * PITCH + n0]);
        const float4 wl = *reinterpret_cast<const float4*>(&sWl[k * PITCH + j0]);
        const float4 wr = *reinterpret_cast<const float4*>(&sWr[k * PITCH + j0]);
        const float amv[4] = {am.x, am.y, am.z, am.w};
        const float axv[4] = {ax.x, ax.y, ax.z, ax.w};
        const float wlv[4] = {wl.x, wl.y, wl.z, wl.w};
        const float wrv[4] = {wr.x, wr.y, wr.z, wr.w};
#pragma unroll
        for (int ni = 0; ni < 4; ni++)
#pragma unroll
            for (int ji = 0; ji < 4; ji++)
                acc[ni][ji] += amv[ni] * wlv[ji] + axv[ni] * wrv[ji];
    }

    const float bv0 = __ldg(&bl[j0 + 0]);
    const float bv1 = __ldg(&bl[j0 + 1]);
    const float bv2 = __ldg(&bl[j0 + 2]);
    const float bv3 = __ldg(&bl[j0 + 3]);

    if (!do_pool) {
#pragma unroll
        for (int ni = 0; ni < 4; ni++) {
            int node = base + n0 + ni;
            if (node < N) {
                float4 v;
                v.x = fmaxf(acc[ni][0] + bv0, 0.f);
                v.y = fmaxf(acc[ni][1] + bv1, 0.f);
                v.z = fmaxf(acc[ni][2] + bv2, 0.f);
                v.w = fmaxf(acc[ni][3] + bv3, 0.f);
                *reinterpret_cast<float4*>(&hout[(size_t)node * 64 + j0]) = v;
            }
        }
    } else {
        __syncthreads();  // done reading sM; reuse it as [n][j] tile
#pragma unroll
        for (int ni = 0; ni < 4; ni++) {
            int n = n0 + ni;
            int node = base + n;
            float4 v;
            if (node < N) {
                v.x = acc[ni][0] + bv0;
                v.y = acc[ni][1] + bv1;
                v.z = acc[ni][2] + bv2;
                v.w = acc[ni][3] + bv3;
            } else {
                v = make_float4(0.f, 0.f, 0.f, 0.f);
            }
            *reinterpret_cast<float4*>(&sM[n * PITCH + j0]) = v;
        }
        __syncthreads();
        if (tid < 64) {
            const int j = tid;
            int cur = sBat[0];
            float sum = 0.f;
#pragma unroll 4
            for (int n = 0; n < 64; n++) {
                int b = sBat[n];
                if (b != cur) {
                    atomicAdd(&pool_out[cur * 64 + j], sum);
                    sum = 0.f;
                    cur = b;
                }
                sum += sM[n * PITCH + j];
            }
            atomicAdd(&pool_out[cur * 64 + j], sum);
        }
    }
}

// ---------------------------------------------------------------------------
// Finalize: counts via binary search on sorted batch, divide pooled sums.
// ---------------------------------------------------------------------------
__global__ __launch_bounds__(256) void finalize_kernel(float* __restrict__ out,
                                                       const int* __restrict__ batch,
                                                       int N) {
    __shared__ int s_cnt[64];
    int tid = threadIdx.x;
    if (tid < 64) {
        int lo0 = 0, hi = N;
        while (lo0 < hi) { int mid = (lo0 + hi) >> 1; if (__ldg(&batch[mid]) < tid) lo0 = mid + 1; else hi = mid; }
        int lo1 = lo0; hi = N;
        while (lo1 < hi) { int mid = (lo1 + hi) >> 1; if (__ldg(&batch[mid]) < tid + 1) lo1 = mid + 1; else hi = mid; }
        s_cnt[tid] = lo1 - lo0;
    }
    __syncthreads();
    for (int i = tid; i < 64 * 64; i += 256) {
        float c = (float)s_cnt[i >> 6];
        out[i] = out[i] / fmaxf(c, 1.0f);
    }
}

// ---------------------------------------------------------------------------
// kernel_launch
// Inputs (metadata order): x, edge_index, edge_attr, batch, edge_emb,
//                          W1_l, b1_l, W1_r, W2_l, b2_l, W2_r
// ---------------------------------------------------------------------------
extern "C" void kernel_launch(void* const* d_in, const int* in_sizes, int n_in,
                              void* d_out, int out_size) {
    const float* x     = (const float*)d_in[0];
    const int*   eidx  = (const int*)d_in[1];
    const int*   batch = (const int*)d_in[3];
    const float* W1l   = (const float*)d_in[5];
    const float* b1l   = (const float*)d_in[6];
    const float* W1r   = (const float*)d_in[7];
    const float* W2l   = (const float*)d_in[8];
    const float* b2l   = (const float*)d_in[9];
    const float* W2r   = (const float*)d_in[10];
    float*       out   = (float*)d_out;

    const int N = in_sizes[3];
    const int E = in_sizes[1] / 2;
    const int* src = eidx;
    const int* dst = eidx + E;

    void* hp = nullptr;
    cudaGetSymbolAddress(&hp, g_h);
    float* hptr = (float*)hp;

    const int smem = (4 * 64 * PITCH + 64) * (int)sizeof(float) + 64 * (int)sizeof(int);
    cudaFuncSetAttribute(sage_kernel, cudaFuncAttributeMaxDynamicSharedMemorySize, smem);

    const int nchunk = (N + CHUNK - 1) / CHUNK;
    const int n_pad  = nchunk * CHUNK;          // <= MAXN
    const int zb     = (n_pad + 255) / 256;
    const int eblk   = (E + 255) / 256;
    const int ablk   = (N + 15) / 16;
    const int gblk   = (N + 63) / 64;

    // CSR build (once; reused by both layers)
    zero_kernel<<<zb, 256>>>(n_pad, N, out, out_size);
    hist_kernel<<<eblk, 256>>>(dst, E);
    scan_chunk_kernel<<<nchunk, 256>>>();
    scan_tops_kernel<<<1, 128>>>(nchunk);
    add_base_kernel<<<(n_pad + 255) / 256, 256>>>(n_pad);
    fill_kernel<<<eblk, 256>>>(src, dst, E);

    // Layer 1
    agg_kernel<<<ablk, 256>>>(x, N);
    sage_kernel<<<gblk, 256, smem>>>(x, W1l, b1l, W1r, hptr, nullptr, nullptr, N, 0);

    // Layer 2 + pool
    agg_kernel<<<ablk, 256>>>(hptr, N);
    sage_kernel<<<gblk, 256, smem>>>(hptr, W2l, b2l, W2r, nullptr, batch, out, N, 1);

    finalize_kernel<<<1, 256>>>(out, batch, N);
}

// round 3
// speedup vs baseline: 1.2693x; 1.0588x over previous
#include <cuda_runtime.h>
#include <cuda_bf16.h>

#define D        64
#define MAXN     100352           // padded to multiple of 1024 (scan chunks)
#define MAXE     1000000
#define PITCH    68               // smem row pitch (floats), multiple of 4 for LDS.128
#define CHUNK    1024

// Packed fp32x2 ops (Blackwell: doubles fp32 FMA throughput vs scalar FFMA).
#define FMA2(d, a, b, c) \
    asm("fma.rn.f32x2 %0, %1, %2, %3;" : "=l"(d) : "l"(a), "l"(b), "l"(c))
#define DUP2(d, v) \
    asm("mov.b64 %0, {%1, %1};" : "=l"(d) : "r"(__float_as_uint(v)))
#define UNPK2(lo, hi, p) \
    asm("mov.b64 {%0, %1}, %2;" : "=r"(lo), "=r"(hi) : "l"(p))

// Static device scratch (no allocations allowed).
__device__ float g_agg[(size_t)MAXN * D];   // aggregation result (both layers)
__device__ float g_h[(size_t)MAXN * D];     // layer-1 output
__device__ int   g_cnt[MAXN];               // in-degree histogram (padded, zeroed)
__device__ int   g_off[MAXN];               // exclusive-scan offsets
__device__ int   g_cursor[MAXN];            // fill cursors
__device__ int   g_srcs[MAXE];              // src node per dst-sorted edge
__device__ int   g_chunksum[128];           // per-chunk totals

// ---------------------------------------------------------------------------
// k0: zero histogram (padded), cursors, and the pooled output.
// ---------------------------------------------------------------------------
__global__ __launch_bounds__(256) void zero_kernel(int n_pad, int n_cur,
                                                   float* __restrict__ out, int n_out) {
    int i = blockIdx.x * 256 + threadIdx.x;
    if (i < n_pad) g_cnt[i] = 0;
    if (i < n_cur) g_cursor[i] = 0;
    if (i < n_out) out[i] = 0.f;
}

// ---------------------------------------------------------------------------
// k1: in-degree histogram over dst.
// ---------------------------------------------------------------------------
__global__ __launch_bounds__(256) void hist_kernel(const int* __restrict__ dst, int E) {
    int e = blockIdx.x * 256 + threadIdx.x;
    if (e < E) atomicAdd(&g_cnt[__ldg(&dst[e])], 1);
}

// ---------------------------------------------------------------------------
// k2: per-chunk (1024) exclusive scan of g_cnt -> g_off, chunk total -> g_chunksum.
// ---------------------------------------------------------------------------
__global__ __launch_bounds__(256) void scan_chunk_kernel() {
    __shared__ int w[256];
    int t = threadIdx.x;
    int base = blockIdx.x * CHUNK + t * 4;
    int4 c = *reinterpret_cast<const int4*>(&g_cnt[base]);
    int s0 = c.x, s1 = s0 + c.y, s2 = s1 + c.z, s3 = s2 + c.w;
    w[t] = s3;
    __syncthreads();
#pragma unroll
    for (int off = 1; off < 256; off <<= 1) {
        int v = (t >= off) ? w[t - off] : 0;
        __syncthreads();
        w[t] += v;
        __syncthreads();
    }
    int excl = (t > 0) ? w[t - 1] : 0;
    int4 o;
    o.x = excl; o.y = excl + s0; o.z = excl + s1; o.w = excl + s2;
    *reinterpret_cast<int4*>(&g_off[base]) = o;
    if (t == 255) g_chunksum[blockIdx.x] = w[255];
}

// ---------------------------------------------------------------------------
// k3: add chunk bases; each block redundantly scans the <=128 chunk sums.
// ---------------------------------------------------------------------------
__global__ __launch_bounds__(256) void add_base_kernel(int n_pad, int nchunk) {
    __shared__ int s[128];
    int t = threadIdx.x;
    if (t < 128) s[t] = (t < nchunk) ? g_chunksum[t] : 0;
    __syncthreads();
#pragma unroll
    for (int off = 1; off < 128; off <<= 1) {
        int v = 0;
        if (t < 128 && t >= off) v = s[t - off];
        __syncthreads();
        if (t < 128) s[t] += v;
        __syncthreads();
    }
    int i = blockIdx.x * 256 + t;
    if (i < n_pad) {
        int c = i >> 10;
        g_off[i] += (c > 0) ? s[c - 1] : 0;
    }
}

// ---------------------------------------------------------------------------
// k4: fill dst-sorted src list.
// ---------------------------------------------------------------------------
__global__ __launch_bounds__(256) void fill_kernel(const int* __restrict__ src,
                                                   const int* __restrict__ dst, int E) {
    int e = blockIdx.x * 256 + threadIdx.x;
    if (e >= E) return;
    int d = __ldg(&dst[e]);
    int p = atomicAdd(&g_cursor[d], 1);
    g_srcs[g_off[d] + p] = __ldg(&src[e]);
}

// ---------------------------------------------------------------------------
// Gather aggregation: 16 threads per dst node, float4 lanes, unroll-2 over edges.
// ---------------------------------------------------------------------------
__global__ __launch_bounds__(256) void agg_kernel(const float* __restrict__ feat, int N) {
    int g = blockIdx.x * 16 + (threadIdx.x >> 4);
    if (g >= N) return;
    int lane = threadIdx.x & 15;
    int start = g_off[g];
    int cnt   = g_cnt[g];
    const float4* f4 = reinterpret_cast<const float4*>(feat);
    float4 a0 = make_float4(0.f, 0.f, 0.f, 0.f);
    float4 a1 = make_float4(0.f, 0.f, 0.f, 0.f);
    int i = 0;
    for (; i + 2 <= cnt; i += 2) {
        int s0 = __ldg(&g_srcs[start + i]);
        int s1 = __ldg(&g_srcs[start + i + 1]);
        float4 v0 = __ldg(f4 + (size_t)s0 * 16 + lane);
        float4 v1 = __ldg(f4 + (size_t)s1 * 16 + lane);
        a0.x += v0.x; a0.y += v0.y; a0.z += v0.z; a0.w += v0.w;
        a1.x += v1.x; a1.y += v1.y; a1.z += v1.z; a1.w += v1.w;
    }
    if (i < cnt) {
        int s0 = __ldg(&g_srcs[start + i]);
        float4 v0 = __ldg(f4 + (size_t)s0 * 16 + lane);
        a0.x += v0.x; a0.y += v0.y; a0.z += v0.z; a0.w += v0.w;
    }
    a0.x += a1.x; a0.y += a1.y; a0.z += a1.z; a0.w += a1.w;
    reinterpret_cast<float4*>(g_agg)[(size_t)g * 16 + lane] = a0;
}

// ---------------------------------------------------------------------------
// Fused SAGE layer with packed f32x2 FMA micro-kernel.
// out = act( (agg/deg) @ Wl^T + b + x @ Wr^T )
//   do_pool=0 : act = relu, write to hout
//   do_pool=1 : no relu, segmented block-local pool into pool_out (atomics)
// Tile: 64 nodes x 64 outs per block, 256 threads, 4x4 register micro-tiles
// (accumulators packed in pairs along j).
// ---------------------------------------------------------------------------
__global__ __launch_bounds__(256) void sage_kernel(const float* __restrict__ xin,
                                                   const float* __restrict__ Wl,
                                                   const float* __restrict__ bl,
                                                   const float* __restrict__ Wr,
                                                   float* __restrict__ hout,
                                                   const int* __restrict__ batch,
                                                   float* __restrict__ pool_out,
                                                   int N, int do_pool) {
    extern __shared__ float sm[];
    float* sM    = sm;                    // 64*PITCH
    float* sX    = sm + 64 * PITCH;
    float* sWl   = sm + 2 * 64 * PITCH;
    float* sWr   = sm + 3 * 64 * PITCH;
    float* sRdeg = sm + 4 * 64 * PITCH;   // 64
    int*   sBat  = reinterpret_cast<int*>(sRdeg + 64); // 64

    const int tid  = threadIdx.x;
    const int base = blockIdx.x * 64;

    if (tid < 64) {
        int node = base + tid;
        float dg = (node < N) ? (float)g_cnt[node] : 1.0f;
        sRdeg[tid] = 1.0f / fmaxf(dg, 1.0f);
        sBat[tid]  = (do_pool && node < N) ? __ldg(&batch[node]) : 0;
    }
    __syncthreads();

    // Cooperative transposed loads.
    for (int i = tid; i < 4096; i += 256) {
        int n = i >> 6, k = i & 63;
        int node = base + n;
        float m = 0.f, xv = 0.f;
        if (node < N) {
            m  = g_agg[(size_t)node * 64 + k] * sRdeg[n];
            xv = __ldg(&xin[(size_t)node * 64 + k]);
        }
        sM[k * PITCH + n] = m;
        sX[k * PITCH + n] = xv;
        sWl[k * PITCH + n] = __ldg(&Wl[i]);
        sWr[k * PITCH + n] = __ldg(&Wr[i]);
    }
    __syncthreads();

    const int n0 = (tid & 15) * 4;
    const int j0 = (tid >> 4) * 4;

    // 8 packed accumulators: acc[ni][jp] = (out[n0+ni][j0+2*jp], out[..][j0+2*jp+1])
    unsigned long long acc[4][2];
#pragma unroll
    for (int a = 0; a < 4; a++) { acc[a][0] = 0ULL; acc[a][1] = 0ULL; }

#pragma unroll 4
    for (int k = 0; k < 64; ++k) {
        const float4 am = *reinterpret_cast<const float4*>(&sM[k * PITCH + n0]);
        const float4 ax = *reinterpret_cast<const float4*>(&sX[k * PITCH + n0]);
        const unsigned long long* wlp =
            reinterpret_cast<const unsigned long long*>(&sWl[k * PITCH + j0]);
        const unsigned long long* wrp =
            reinterpret_cast<const unsigned long long*>(&sWr[k * PITCH + j0]);
        const unsigned long long wl01 = wlp[0], wl23 = wlp[1];
        const unsigned long long wr01 = wrp[0], wr23 = wrp[1];

        unsigned long long da[4], dx[4];
        DUP2(da[0], am.x); DUP2(da[1], am.y); DUP2(da[2], am.z); DUP2(da[3], am.w);
        DUP2(dx[0], ax.x); DUP2(dx[1], ax.y); DUP2(dx[2], ax.z); DUP2(dx[3], ax.w);

#pragma unroll
        for (int ni = 0; ni < 4; ni++) {
            FMA2(acc[ni][0], da[ni], wl01, acc[ni][0]);
            FMA2(acc[ni][1], da[ni], wl23, acc[ni][1]);
        }
#pragma unroll
        for (int ni = 0; ni < 4; ni++) {
            FMA2(acc[ni][0], dx[ni], wr01, acc[ni][0]);
            FMA2(acc[ni][1], dx[ni], wr23, acc[ni][1]);
        }
    }

    const float bv0 = __ldg(&bl[j0 + 0]);
    const float bv1 = __ldg(&bl[j0 + 1]);
    const float bv2 = __ldg(&bl[j0 + 2]);
    const float bv3 = __ldg(&bl[j0 + 3]);

    float res[4][4];
#pragma unroll
    for (int ni = 0; ni < 4; ni++) {
        unsigned r0, r1, r2, r3;
        UNPK2(r0, r1, acc[ni][0]);
        UNPK2(r2, r3, acc[ni][1]);
        res[ni][0] = __uint_as_float(r0) + bv0;
        res[ni][1] = __uint_as_float(r1) + bv1;
        res[ni][2] = __uint_as_float(r2) + bv2;
        res[ni][3] = __uint_as_float(r3) + bv3;
    }

    if (!do_pool) {
#pragma unroll
        for (int ni = 0; ni < 4; ni++) {
            int node = base + n0 + ni;
            if (node < N) {
                float4 v;
                v.x = fmaxf(res[ni][0], 0.f);
                v.y = fmaxf(res[ni][1], 0.f);
                v.z = fmaxf(res[ni][2], 0.f);
                v.w = fmaxf(res[ni][3], 0.f);
                *reinterpret_cast<float4*>(&hout[(size_t)node * 64 + j0]) = v;
            }
        }
    } else {
        __syncthreads();  // done reading sM; reuse it as [n][j] tile
#pragma unroll
        for (int ni = 0; ni < 4; ni++) {
            int n = n0 + ni;
            int node = base + n;
            float4 v;
            if (node < N) {
                v.x = res[ni][0]; v.y = res[ni][1]; v.z = res[ni][2]; v.w = res[ni][3];
            } else {
                v = make_float4(0.f, 0.f, 0.f, 0.f);
            }
            *reinterpret_cast<float4*>(&sM[n * PITCH + j0]) = v;
        }
        __syncthreads();
        if (tid < 64) {
            const int j = tid;
            int cur = sBat[0];
            float sum = 0.f;
#pragma unroll 4
            for (int n = 0; n < 64; n++) {
                int b = sBat[n];
                if (b != cur) {
                    atomicAdd(&pool_out[cur * 64 + j], sum);
                    sum = 0.f;
                    cur = b;
                }
                sum += sM[n * PITCH + j];
            }
            atomicAdd(&pool_out[cur * 64 + j], sum);
        }
    }
}

// ---------------------------------------------------------------------------
// Finalize: counts via binary search on sorted batch, divide pooled sums.
// ---------------------------------------------------------------------------
__global__ __launch_bounds__(256) void finalize_kernel(float* __restrict__ out,
                                                       const int* __restrict__ batch,
                                                       int N) {
    __shared__ int s_cnt[64];
    int tid = threadIdx.x;
    if (tid < 64) {
        int lo0 = 0, hi = N;
        while (lo0 < hi) { int mid = (lo0 + hi) >> 1; if (__ldg(&batch[mid]) < tid) lo0 = mid + 1; else hi = mid; }
        int lo1 = lo0; hi = N;
        while (lo1 < hi) { int mid = (lo1 + hi) >> 1; if (__ldg(&batch[mid]) < tid + 1) lo1 = mid + 1; else hi = mid; }
        s_cnt[tid] = lo1 - lo0;
    }
    __syncthreads();
    for (int i = tid; i < 64 * 64; i += 256) {
        float c = (float)s_cnt[i >> 6];
        out[i] = out[i] / fmaxf(c, 1.0f);
    }
}

// ---------------------------------------------------------------------------
// kernel_launch
// Inputs (metadata order): x, edge_index, edge_attr, batch, edge_emb,
//                          W1_l, b1_l, W1_r, W2_l, b2_l, W2_r
// ---------------------------------------------------------------------------
extern "C" void kernel_launch(void* const* d_in, const int* in_sizes, int n_in,
                              void* d_out, int out_size) {
    const float* x     = (const float*)d_in[0];
    const int*   eidx  = (const int*)d_in[1];
    const int*   batch = (const int*)d_in[3];
    const float* W1l   = (const float*)d_in[5];
    const float* b1l   = (const float*)d_in[6];
    const float* W1r   = (const float*)d_in[7];
    const float* W2l   = (const float*)d_in[8];
    const float* b2l   = (const float*)d_in[9];
    const float* W2r   = (const float*)d_in[10];
    float*       out   = (float*)d_out;

    const int N = in_sizes[3];
    const int E = in_sizes[1] / 2;
    const int* src = eidx;
    const int* dst = eidx + E;

    void* hp = nullptr;
    cudaGetSymbolAddress(&hp, g_h);
    float* hptr = (float*)hp;

    const int smem = (4 * 64 * PITCH + 64) * (int)sizeof(float) + 64 * (int)sizeof(int);
    cudaFuncSetAttribute(sage_kernel, cudaFuncAttributeMaxDynamicSharedMemorySize, smem);

    const int nchunk = (N + CHUNK - 1) / CHUNK;
    const int n_pad  = nchunk * CHUNK;          // <= MAXN
    const int zb     = (n_pad + 255) / 256;
    const int eblk   = (E + 255) / 256;
    const int ablk   = (N + 15) / 16;
    const int gblk   = (N + 63) / 64;

    // CSR build (once; reused by both layers)
    zero_kernel<<<zb, 256>>>(n_pad, N, out, out_size);
    hist_kernel<<<eblk, 256>>>(dst, E);
    scan_chunk_kernel<<<nchunk, 256>>>();
    add_base_kernel<<<(n_pad + 255) / 256, 256>>>(n_pad, nchunk);
    fill_kernel<<<eblk, 256>>>(src, dst, E);

    // Layer 1
    agg_kernel<<<ablk, 256>>>(x, N);
    sage_kernel<<<gblk, 256, smem>>>(x, W1l, b1l, W1r, hptr, nullptr, nullptr, N, 0);

    // Layer 2 + pool
    agg_kernel<<<ablk, 256>>>(hptr, N);
    sage_kernel<<<gblk, 256, smem>>>(hptr, W2l, b2l, W2r, nullptr, batch, out, N, 1);

    finalize_kernel<<<1, 256>>>(out, batch, N);
}

// round 4
// speedup vs baseline: 1.3252x; 1.0440x over previous
#include <cuda_runtime.h>
#include <cuda_bf16.h>

#define D        64
#define MAXN     100352           // padded to multiple of 1024 (scan chunks)
#define MAXE     1000000
#define CHUNK    1024
#define BN       128              // nodes per sage block
#define PA       132              // smem pitch for A tiles (floats)
#define PW       68               // smem pitch for W tiles (floats)

typedef unsigned long long u64;

// Packed fp32x2 ops (Blackwell).
#define FMA2(d, a, b, c) \
    asm("fma.rn.f32x2 %0, %1, %2, %3;" : "=l"(d) : "l"(a), "l"(b), "l"(c))
#define DUP2(d, v) \
    asm("mov.b64 %0, {%1, %1};" : "=l"(d) : "r"(__float_as_uint(v)))
#define UNPK2(lo, hi, p) \
    asm("mov.b64 {%0, %1}, %2;" : "=r"(lo), "=r"(hi) : "l"(p))

// Static device scratch.
__device__ float g_agg[(size_t)MAXN * D];
__device__ float g_h[(size_t)MAXN * D];
__device__ int   g_cnt[MAXN];
__device__ int   g_off[MAXN];
__device__ int   g_srcs[MAXE];
__device__ int   g_chunksum[128];
__device__ float g_rbc[64];        // 1/max(count(batch==b),1)

// ---------------------------------------------------------------------------
// k0: zero histogram + pooled output; block 0 computes per-graph 1/counts.
// ---------------------------------------------------------------------------
__global__ __launch_bounds__(256) void zero_kernel(int n_pad, float* __restrict__ out,
                                                   int n_out, const int* __restrict__ batch,
                                                   int N) {
    int i = blockIdx.x * 256 + threadIdx.x;
    if (i < n_pad) g_cnt[i] = 0;
    if (i < n_out) out[i] = 0.f;
    if (blockIdx.x == 0 && threadIdx.x < 64) {
        int b = threadIdx.x;
        int lo0 = 0, hi = N;
        while (lo0 < hi) { int mid = (lo0 + hi) >> 1; if (__ldg(&batch[mid]) < b) lo0 = mid + 1; else hi = mid; }
        int lo1 = lo0; hi = N;
        while (lo1 < hi) { int mid = (lo1 + hi) >> 1; if (__ldg(&batch[mid]) < b + 1) lo1 = mid + 1; else hi = mid; }
        g_rbc[b] = 1.0f / fmaxf((float)(lo1 - lo0), 1.0f);
    }
}

// ---------------------------------------------------------------------------
// k1: in-degree histogram over dst.
// ---------------------------------------------------------------------------
__global__ __launch_bounds__(256) void hist_kernel(const int* __restrict__ dst, int E) {
    int e = blockIdx.x * 256 + threadIdx.x;
    if (e < E) atomicAdd(&g_cnt[__ldg(&dst[e])], 1);
}

// ---------------------------------------------------------------------------
// k2: per-chunk (1024) exclusive scan of g_cnt -> g_off, chunk totals.
// ---------------------------------------------------------------------------
__global__ __launch_bounds__(256) void scan_chunk_kernel() {
    __shared__ int w[256];
    int t = threadIdx.x;
    int base = blockIdx.x * CHUNK + t * 4;
    int4 c = *reinterpret_cast<const int4*>(&g_cnt[base]);
    int s0 = c.x, s1 = s0 + c.y, s2 = s1 + c.z, s3 = s2 + c.w;
    w[t] = s3;
    __syncthreads();
#pragma unroll
    for (int off = 1; off < 256; off <<= 1) {
        int v = (t >= off) ? w[t - off] : 0;
        __syncthreads();
        w[t] += v;
        __syncthreads();
    }
    int excl = (t > 0) ? w[t - 1] : 0;
    int4 o;
    o.x = excl; o.y = excl + s0; o.z = excl + s1; o.w = excl + s2;
    *reinterpret_cast<int4*>(&g_off[base]) = o;
    if (t == 255) g_chunksum[blockIdx.x] = w[255];
}

// ---------------------------------------------------------------------------
// k3: add chunk bases (each block redundantly scans <=128 chunk sums).
// ---------------------------------------------------------------------------
__global__ __launch_bounds__(256) void add_base_kernel(int n_pad, int nchunk) {
    __shared__ int s[128];
    int t = threadIdx.x;
    if (t < 128) s[t] = (t < nchunk) ? g_chunksum[t] : 0;
    __syncthreads();
#pragma unroll
    for (int off = 1; off < 128; off <<= 1) {
        int v = 0;
        if (t < 128 && t >= off) v = s[t - off];
        __syncthreads();
        if (t < 128) s[t] += v;
        __syncthreads();
    }
    int i = blockIdx.x * 256 + t;
    if (i < n_pad) {
        int c = i >> 10;
        g_off[i] += (c > 0) ? s[c - 1] : 0;
    }
}

// ---------------------------------------------------------------------------
// k4: fill dst-sorted src list. Bumps g_off in place (becomes end offsets).
// ---------------------------------------------------------------------------
__global__ __launch_bounds__(256) void fill_kernel(const int* __restrict__ src,
                                                   const int* __restrict__ dst, int E) {
    int e = blockIdx.x * 256 + threadIdx.x;
    if (e >= E) return;
    int d = __ldg(&dst[e]);
    int p = atomicAdd(&g_off[d], 1);
    g_srcs[p] = __ldg(&src[e]);
}

// ---------------------------------------------------------------------------
// Gather aggregation: 16 threads per dst node. start = end_off - cnt.
// ---------------------------------------------------------------------------
__global__ __launch_bounds__(256) void agg_kernel(const float* __restrict__ feat, int N) {
    int g = blockIdx.x * 16 + (threadIdx.x >> 4);
    if (g >= N) return;
    int lane = threadIdx.x & 15;
    int cnt   = g_cnt[g];
    int start = g_off[g] - cnt;
    const float4* f4 = reinterpret_cast<const float4*>(feat);
    float4 a0 = make_float4(0.f, 0.f, 0.f, 0.f);
    float4 a1 = make_float4(0.f, 0.f, 0.f, 0.f);
    int i = 0;
    for (; i + 2 <= cnt; i += 2) {
        int s0 = __ldg(&g_srcs[start + i]);
        int s1 = __ldg(&g_srcs[start + i + 1]);
        float4 v0 = __ldg(f4 + (size_t)s0 * 16 + lane);
        float4 v1 = __ldg(f4 + (size_t)s1 * 16 + lane);
        a0.x += v0.x; a0.y += v0.y; a0.z += v0.z; a0.w += v0.w;
        a1.x += v1.x; a1.y += v1.y; a1.z += v1.z; a1.w += v1.w;
    }
    if (i < cnt) {
        int s0 = __ldg(&g_srcs[start + i]);
        float4 v0 = __ldg(f4 + (size_t)s0 * 16 + lane);
        a0.x += v0.x; a0.y += v0.y; a0.z += v0.z; a0.w += v0.w;
    }
    a0.x += a1.x; a0.y += a1.y; a0.z += a1.z; a0.w += a1.w;
    reinterpret_cast<float4*>(g_agg)[(size_t)g * 16 + lane] = a0;
}

// ---------------------------------------------------------------------------
// Fused SAGE layer, 128-node tile, 4x8 (4 nodes x 4 j-pairs) per thread.
// out = act( (agg/deg) @ Wl^T + b + x @ Wr^T )
//   do_pool=0 : relu -> hout ; do_pool=1 : scaled segmented pool -> pool_out
// ---------------------------------------------------------------------------
__global__ __launch_bounds__(256) void sage_kernel(const float* __restrict__ xin,
                                                   const float* __restrict__ Wl,
                                                   const float* __restrict__ bl,
                                                   const float* __restrict__ Wr,
                                                   float* __restrict__ hout,
                                                   const int* __restrict__ batch,
                                                   float* __restrict__ pool_out,
                                                   int N, int do_pool) {
    extern __shared__ float sm[];
    float* sA    = sm;                        // 64*PA (mean^T)
    float* sX    = sm + 64 * PA;              // 64*PA (x^T)
    float* sWl   = sm + 2 * 64 * PA;          // 64*PW
    float* sWr   = sWl + 64 * PW;             // 64*PW
    float* sRdeg = sWr + 64 * PW;             // 128
    float* sRbc  = sRdeg + BN;                // 64
    int*   sBat  = reinterpret_cast<int*>(sRbc + 64);  // 128

    const int tid  = threadIdx.x;
    const int base = blockIdx.x * BN;

    if (tid < BN) {
        int node = base + tid;
        float dg = (node < N) ? (float)g_cnt[node] : 1.0f;
        sRdeg[tid] = 1.0f / fmaxf(dg, 1.0f);
        sBat[tid]  = (do_pool && node < N) ? __ldg(&batch[node]) : 0;
    }
    if (do_pool && tid >= BN && tid < BN + 64) sRbc[tid - BN] = g_rbc[tid - BN];
    __syncthreads();

    // A tiles (transposed): 128 nodes x 64 k.
    for (int i = tid; i < BN * 64; i += 256) {
        int n = i >> 6, k = i & 63;
        int node = base + n;
        float m = 0.f, xv = 0.f;
        if (node < N) {
            m  = g_agg[(size_t)node * 64 + k] * sRdeg[n];
            xv = __ldg(&xin[(size_t)node * 64 + k]);
        }
        sA[k * PA + n] = m;
        sX[k * PA + n] = xv;
    }
    // W tiles (transposed [k][j]).
    for (int i = tid; i < 4096; i += 256) {
        int j = i >> 6, k = i & 63;
        sWl[k * PW + j] = __ldg(&Wl[i]);
        sWr[k * PW + j] = __ldg(&Wr[i]);
    }
    __syncthreads();

    const int nt = tid & 31;        // 0..31 -> n0 = nt*4
    const int jt = tid >> 5;        // warp id 0..7 -> j0 = jt*8
    const int n0 = nt * 4;
    const int j0 = jt * 8;

    u64 acc[4][4];                  // [node][j-pair]
#pragma unroll
    for (int a = 0; a < 4; a++)
#pragma unroll
        for (int b = 0; b < 4; b++) acc[a][b] = 0ULL;

#pragma unroll 4
    for (int k = 0; k < 64; ++k) {
        const float4 am = *reinterpret_cast<const float4*>(&sA[k * PA + n0]);
        const float4 ax = *reinterpret_cast<const float4*>(&sX[k * PA + n0]);
        const ulonglong2* wlp = reinterpret_cast<const ulonglong2*>(&sWl[k * PW + j0]);
        const ulonglong2* wrp = reinterpret_cast<const ulonglong2*>(&sWr[k * PW + j0]);
        const ulonglong2 wlA = wlp[0], wlB = wlp[1];
        const ulonglong2 wrA = wrp[0], wrB = wrp[1];

        u64 da[4], dx[4];
        DUP2(da[0], am.x); DUP2(da[1], am.y); DUP2(da[2], am.z); DUP2(da[3], am.w);
        DUP2(dx[0], ax.x); DUP2(dx[1], ax.y); DUP2(dx[2], ax.z); DUP2(dx[3], ax.w);

#pragma unroll
        for (int ni = 0; ni < 4; ni++) {
            FMA2(acc[ni][0], da[ni], wlA.x, acc[ni][0]);
            FMA2(acc[ni][1], da[ni], wlA.y, acc[ni][1]);
            FMA2(acc[ni][2], da[ni], wlB.x, acc[ni][2]);
            FMA2(acc[ni][3], da[ni], wlB.y, acc[ni][3]);
        }
#pragma unroll
        for (int ni = 0; ni < 4; ni++) {
            FMA2(acc[ni][0], dx[ni], wrA.x, acc[ni][0]);
            FMA2(acc[ni][1], dx[ni], wrA.y, acc[ni][1]);
            FMA2(acc[ni][2], dx[ni], wrB.x, acc[ni][2]);
            FMA2(acc[ni][3], dx[ni], wrB.y, acc[ni][3]);
        }
    }

    float bv[8];
    {
        const float4 b0 = __ldg(reinterpret_cast<const float4*>(&bl[j0]));
        const float4 b1 = __ldg(reinterpret_cast<const float4*>(&bl[j0 + 4]));
        bv[0] = b0.x; bv[1] = b0.y; bv[2] = b0.z; bv[3] = b0.w;
        bv[4] = b1.x; bv[5] = b1.y; bv[6] = b1.z; bv[7] = b1.w;
    }

    float res[4][8];
#pragma unroll
    for (int ni = 0; ni < 4; ni++) {
#pragma unroll
        for (int jp = 0; jp < 4; jp++) {
            unsigned lo, hi;
            UNPK2(lo, hi, acc[ni][jp]);
            res[ni][2 * jp]     = __uint_as_float(lo) + bv[2 * jp];
            res[ni][2 * jp + 1] = __uint_as_float(hi) + bv[2 * jp + 1];
        }
    }

    if (!do_pool) {
#pragma unroll
        for (int ni = 0; ni < 4; ni++) {
            int node = base + n0 + ni;
            if (node < N) {
                float4 v0, v1;
                v0.x = fmaxf(res[ni][0], 0.f); v0.y = fmaxf(res[ni][1], 0.f);
                v0.z = fmaxf(res[ni][2], 0.f); v0.w = fmaxf(res[ni][3], 0.f);
                v1.x = fmaxf(res[ni][4], 0.f); v1.y = fmaxf(res[ni][5], 0.f);
                v1.z = fmaxf(res[ni][6], 0.f); v1.w = fmaxf(res[ni][7], 0.f);
                float4* p = reinterpret_cast<float4*>(&hout[(size_t)node * 64 + j0]);
                p[0] = v0; p[1] = v1;
            }
        }
    } else {
        __syncthreads();  // done reading sA/sX; reuse as [n][j] pool buffer (pitch PW)
        float* pb = sm;   // 128*PW floats < 2*64*PA  ✓
#pragma unroll
        for (int ni = 0; ni < 4; ni++) {
            int n = n0 + ni;
            int node = base + n;
            float4 v0, v1;
            if (node < N) {
                v0.x = res[ni][0]; v0.y = res[ni][1]; v0.z = res[ni][2]; v0.w = res[ni][3];
                v1.x = res[ni][4]; v1.y = res[ni][5]; v1.z = res[ni][6]; v1.w = res[ni][7];
            } else {
                v0 = make_float4(0.f, 0.f, 0.f, 0.f);
                v1 = v0;
            }
            float4* p = reinterpret_cast<float4*>(&pb[n * PW + j0]);
            p[0] = v0; p[1] = v1;
        }
        __syncthreads();
        if (tid < 64) {
            const int j = tid;
            int cur = sBat[0];
            float sum = 0.f;
#pragma unroll 4
            for (int n = 0; n < BN; n++) {
                int b = sBat[n];
                if (b != cur) {
                    atomicAdd(&pool_out[cur * 64 + j], sum * sRbc[cur]);
                    sum = 0.f;
                    cur = b;
                }
                sum += pb[n * PW + j];
            }
            atomicAdd(&pool_out[cur * 64 + j], sum * sRbc[cur]);
        }
    }
}

// ---------------------------------------------------------------------------
// kernel_launch
// Inputs: x, edge_index, edge_attr, batch, edge_emb,
//         W1_l, b1_l, W1_r, W2_l, b2_l, W2_r
// ---------------------------------------------------------------------------
extern "C" void kernel_launch(void* const* d_in, const int* in_sizes, int n_in,
                              void* d_out, int out_size) {
    const float* x     = (const float*)d_in[0];
    const int*   eidx  = (const int*)d_in[1];
    const int*   batch = (const int*)d_in[3];
    const float* W1l   = (const float*)d_in[5];
    const float* b1l   = (const float*)d_in[6];
    const float* W1r   = (const float*)d_in[7];
    const float* W2l   = (const float*)d_in[8];
    const float* b2l   = (const float*)d_in[9];
    const float* W2r   = (const float*)d_in[10];
    float*       out   = (float*)d_out;

    const int N = in_sizes[3];
    const int E = in_sizes[1] / 2;
    const int* src = eidx;
    const int* dst = eidx + E;

    void* hp = nullptr;
    cudaGetSymbolAddress(&hp, g_h);
    float* hptr = (float*)hp;

    const int smem = (2 * 64 * PA + 2 * 64 * PW + BN + 64) * (int)sizeof(float)
                     + BN * (int)sizeof(int);
    cudaFuncSetAttribute(sage_kernel, cudaFuncAttributeMaxDynamicSharedMemorySize, smem);

    const int nchunk = (N + CHUNK - 1) / CHUNK;
    const int n_pad  = nchunk * CHUNK;
    const int zb     = (n_pad + 255) / 256;
    const int eblk   = (E + 255) / 256;
    const int ablk   = (N + 15) / 16;
    const int gblk   = (N + BN - 1) / BN;

    // CSR build (once; reused by both layers)
    zero_kernel<<<zb, 256>>>(n_pad, out, out_size, batch, N);
    hist_kernel<<<eblk, 256>>>(dst, E);
    scan_chunk_kernel<<<nchunk, 256>>>();
    add_base_kernel<<<(n_pad + 255) / 256, 256>>>(n_pad, nchunk);
    fill_kernel<<<eblk, 256>>>(src, dst, E);

    // Layer 1
    agg_kernel<<<ablk, 256>>>(x, N);
    sage_kernel<<<gblk, 256, smem>>>(x, W1l, b1l, W1r, hptr, nullptr, nullptr, N, 0);

    // Layer 2 + fused scaled pool
    agg_kernel<<<ablk, 256>>>(hptr, N);
    sage_kernel<<<gblk, 256, smem>>>(hptr, W2l, b2l, W2r, nullptr, batch, out, N, 1);
}

// round 5
// speedup vs baseline: 1.4665x; 1.1066x over previous
#include <cuda_runtime.h>
#include <cuda_fp16.h>

#define D        64
#define MAXN     100352           // padded to multiple of 1024 (scan chunks)
#define MAXE     1000000
#define CHUNK    1024
#define BN       128              // nodes per sage block
#define PA       132              // smem pitch for A tiles (floats)
#define PW       68               // smem pitch for W tiles (floats)

typedef unsigned long long u64;

// Packed fp32x2 ops (Blackwell).
#define FMA2(d, a, b, c) \
    asm("fma.rn.f32x2 %0, %1, %2, %3;" : "=l"(d) : "l"(a), "l"(b), "l"(c))
#define DUP2(d, v) \
    asm("mov.b64 %0, {%1, %1};" : "=l"(d) : "r"(__float_as_uint(v)))
#define UNPK2(lo, hi, p) \
    asm("mov.b64 {%0, %1}, %2;" : "=r"(lo), "=r"(hi) : "l"(p))

static __device__ __forceinline__ unsigned pack_h2(float a, float b) {
    __half2 h = __floats2half2_rn(a, b);
    return *reinterpret_cast<unsigned*>(&h);
}

// Static device scratch.
__device__ float  g_agg[(size_t)MAXN * D];
__device__ __half g_x16[(size_t)MAXN * D];
__device__ __half g_h16[(size_t)MAXN * D];
__device__ int    g_cnt[MAXN];
__device__ int    g_off[MAXN];
__device__ int    g_srcs[MAXE];
__device__ int    g_chunksum[128];
__device__ int    g_chunkbase[128];
__device__ int    g_done;
__device__ float  g_rbc[64];       // 1/max(count(batch==b),1)

// ---------------------------------------------------------------------------
// k0: zero histogram/flags/pool output, convert x -> fp16, per-graph 1/counts.
// Grid sized to cover n4 = N*16 float4s.
// ---------------------------------------------------------------------------
__global__ __launch_bounds__(256) void zero_kernel(int n_pad, float* __restrict__ out,
                                                   int n_out, const int* __restrict__ batch,
                                                   int N, const float4* __restrict__ x4,
                                                   int n4) {
    int i = blockIdx.x * 256 + threadIdx.x;
    if (i < n_pad) g_cnt[i] = 0;
    if (i < n_out) out[i] = 0.f;
    if (i == 0) g_done = 0;
    if (i < n4) {
        float4 v = __ldg(&x4[i]);
        uint2 p;
        p.x = pack_h2(v.x, v.y);
        p.y = pack_h2(v.z, v.w);
        reinterpret_cast<uint2*>(g_x16)[i] = p;
    }
    if (blockIdx.x == 0 && threadIdx.x < 64) {
        int b = threadIdx.x;
        int lo0 = 0, hi = N;
        while (lo0 < hi) { int mid = (lo0 + hi) >> 1; if (__ldg(&batch[mid]) < b) lo0 = mid + 1; else hi = mid; }
        int lo1 = lo0; hi = N;
        while (lo1 < hi) { int mid = (lo1 + hi) >> 1; if (__ldg(&batch[mid]) < b + 1) lo1 = mid + 1; else hi = mid; }
        g_rbc[b] = 1.0f / fmaxf((float)(lo1 - lo0), 1.0f);
    }
}

// ---------------------------------------------------------------------------
// k1: in-degree histogram over dst.
// ---------------------------------------------------------------------------
__global__ __launch_bounds__(256) void hist_kernel(const int* __restrict__ dst, int E) {
    int e = blockIdx.x * 256 + threadIdx.x;
    if (e < E) atomicAdd(&g_cnt[__ldg(&dst[e])], 1);
}

// ---------------------------------------------------------------------------
// k2: per-chunk (1024) exclusive scan of g_cnt -> g_off; last block scans the
// chunk totals into g_chunkbase (decoupled via g_done).
// ---------------------------------------------------------------------------
__global__ __launch_bounds__(256) void scan_chunk_kernel() {
    __shared__ int w[256];
    __shared__ int isLast;
    int t = threadIdx.x;
    int base = blockIdx.x * CHUNK + t * 4;
    int4 c = *reinterpret_cast<const int4*>(&g_cnt[base]);
    int s0 = c.x, s1 = s0 + c.y, s2 = s1 + c.z, s3 = s2 + c.w;
    w[t] = s3;
    __syncthreads();
#pragma unroll
    for (int off = 1; off < 256; off <<= 1) {
        int v = (t >= off) ? w[t - off] : 0;
        __syncthreads();
        w[t] += v;
        __syncthreads();
    }
    int excl = (t > 0) ? w[t - 1] : 0;
    int4 o;
    o.x = excl; o.y = excl + s0; o.z = excl + s1; o.w = excl + s2;
    *reinterpret_cast<int4*>(&g_off[base]) = o;
    if (t == 255) g_chunksum[blockIdx.x] = w[255];

    __threadfence();
    if (t == 0) isLast = (atomicAdd(&g_done, 1) == (int)gridDim.x - 1);
    __syncthreads();
    if (isLast) {
        int v = 0;
        if (t < 128 && t < (int)gridDim.x)
            v = *((volatile int*)&g_chunksum[t]);
        if (t < 128) w[t] = v;
        __syncthreads();
#pragma unroll
        for (int off = 1; off < 128; off <<= 1) {
            int u = 0;
            if (t < 128 && t >= off) u = w[t - off];
            __syncthreads();
            if (t < 128) w[t] += u;
            __syncthreads();
        }
        if (t < 128) g_chunkbase[t] = (t > 0) ? w[t - 1] : 0;
    }
}

// ---------------------------------------------------------------------------
// k3: add chunk bases.
// ---------------------------------------------------------------------------
__global__ __launch_bounds__(256) void add_base_kernel(int n_pad) {
    int i = blockIdx.x * 256 + threadIdx.x;
    if (i < n_pad) g_off[i] += g_chunkbase[i >> 10];
}

// ---------------------------------------------------------------------------
// k4: fill dst-sorted src list. Bumps g_off in place (becomes end offsets).
// ---------------------------------------------------------------------------
__global__ __launch_bounds__(256) void fill_kernel(const int* __restrict__ src,
                                                   const int* __restrict__ dst, int E) {
    int e = blockIdx.x * 256 + threadIdx.x;
    if (e >= E) return;
    int d = __ldg(&dst[e]);
    int p = atomicAdd(&g_off[d], 1);
    g_srcs[p] = __ldg(&src[e]);
}

// ---------------------------------------------------------------------------
// Gather aggregation (fp16 payload): 8 threads per dst node, one uint4
// (8 halves) per lane, shuffle-broadcast edge indices, fp32 accumulation.
// ---------------------------------------------------------------------------
__global__ __launch_bounds__(256) void agg_kernel(const __half* __restrict__ feat, int N) {
    int g = blockIdx.x * 32 + (threadIdx.x >> 3);
    int lane = threadIdx.x & 7;
    unsigned gmask = 0xFFu << ((threadIdx.x & 31) & ~7);
    bool active = (g < N);
    int cnt = active ? g_cnt[g] : 0;
    int start = active ? (g_off[g] - cnt) : 0;
    const uint4* f4 = reinterpret_cast<const uint4*>(feat);   // row = 8 uint4
    float a[8];
#pragma unroll
    for (int c = 0; c < 8; c++) a[c] = 0.f;

    for (int i = 0; i < cnt; i += 8) {
        int my = (i + lane < cnt) ? __ldg(&g_srcs[start + i + lane]) : 0;
        int lim = cnt - i;
#pragma unroll
        for (int e = 0; e < 8; e++) {
            if (e >= lim) break;
            int s = __shfl_sync(gmask, my, e, 8);
            uint4 v = __ldg(f4 + (size_t)s * 8 + lane);
            float2 f0 = __half22float2(*reinterpret_cast<__half2*>(&v.x));
            float2 f1 = __half22float2(*reinterpret_cast<__half2*>(&v.y));
            float2 f2 = __half22float2(*reinterpret_cast<__half2*>(&v.z));
            float2 f3 = __half22float2(*reinterpret_cast<__half2*>(&v.w));
            a[0] += f0.x; a[1] += f0.y; a[2] += f1.x; a[3] += f1.y;
            a[4] += f2.x; a[5] += f2.y; a[6] += f3.x; a[7] += f3.y;
        }
    }
    if (active) {
        float4* o = reinterpret_cast<float4*>(g_agg);
        o[(size_t)g * 16 + lane * 2]     = make_float4(a[0], a[1], a[2], a[3]);
        o[(size_t)g * 16 + lane * 2 + 1] = make_float4(a[4], a[5], a[6], a[7]);
    }
}

// ---------------------------------------------------------------------------
// Fused SAGE layer, 128-node tile, 4 nodes x 4 j-pairs per thread, f32x2 FMA.
// xin is fp16; mean term from g_agg (fp32) / deg.
//   do_pool=0 : relu -> hout16 (fp16) ; do_pool=1 : scaled segmented pool.
// ---------------------------------------------------------------------------
__global__ __launch_bounds__(256) void sage_kernel(const __half* __restrict__ xin16,
                                                   const float* __restrict__ Wl,
                                                   const float* __restrict__ bl,
                                                   const float* __restrict__ Wr,
                                                   __half* __restrict__ hout16,
                                                   const int* __restrict__ batch,
                                                   float* __restrict__ pool_out,
                                                   int N, int do_pool) {
    extern __shared__ float sm[];
    float* sA    = sm;                        // 64*PA (mean^T)
    float* sX    = sm + 64 * PA;              // 64*PA (x^T)
    float* sWl   = sm + 2 * 64 * PA;          // 64*PW
    float* sWr   = sWl + 64 * PW;             // 64*PW
    float* sRdeg = sWr + 64 * PW;             // 128
    float* sRbc  = sRdeg + BN;                // 64
    int*   sBat  = reinterpret_cast<int*>(sRbc + 64);  // 128

    const int tid  = threadIdx.x;
    const int base = blockIdx.x * BN;

    if (tid < BN) {
        int node = base + tid;
        float dg = (node < N) ? (float)g_cnt[node] : 1.0f;
        sRdeg[tid] = 1.0f / fmaxf(dg, 1.0f);
        sBat[tid]  = (do_pool && node < N) ? __ldg(&batch[node]) : 0;
    }
    if (do_pool && tid >= BN && tid < BN + 64) sRbc[tid - BN] = g_rbc[tid - BN];
    __syncthreads();

    // mean tile: i = kq*BN + n (warp spans n -> conflict-free STS).
    const float4* agg4 = reinterpret_cast<const float4*>(g_agg);
    for (int i = tid; i < BN * 16; i += 256) {
        int kq = i >> 7, n = i & 127;
        int node = base + n;
        float4 v = make_float4(0.f, 0.f, 0.f, 0.f);
        if (node < N) {
            v = __ldg(&agg4[(size_t)node * 16 + kq]);
            float r = sRdeg[n];
            v.x *= r; v.y *= r; v.z *= r; v.w *= r;
        }
        sA[(kq * 4 + 0) * PA + n] = v.x;
        sA[(kq * 4 + 1) * PA + n] = v.y;
        sA[(kq * 4 + 2) * PA + n] = v.z;
        sA[(kq * 4 + 3) * PA + n] = v.w;
    }
    // x tile (fp16): i = ko*BN + n, 8 halves per load.
    const uint4* x4 = reinterpret_cast<const uint4*>(xin16);
    for (int i = tid; i < BN * 8; i += 256) {
        int ko = i >> 7, n = i & 127;
        int node = base + n;
        float f[8];
        if (node < N) {
            uint4 v = __ldg(&x4[(size_t)node * 8 + ko]);
            float2 f0 = __half22float2(*reinterpret_cast<__half2*>(&v.x));
            float2 f1 = __half22float2(*reinterpret_cast<__half2*>(&v.y));
            float2 f2 = __half22float2(*reinterpret_cast<__half2*>(&v.z));
            float2 f3 = __half22float2(*reinterpret_cast<__half2*>(&v.w));
            f[0] = f0.x; f[1] = f0.y; f[2] = f1.x; f[3] = f1.y;
            f[4] = f2.x; f[5] = f2.y; f[6] = f3.x; f[7] = f3.y;
        } else {
#pragma unroll
            for (int c = 0; c < 8; c++) f[c] = 0.f;
        }
#pragma unroll
        for (int c = 0; c < 8; c++) sX[(ko * 8 + c) * PA + n] = f[c];
    }
    // W tiles (transposed [k][j]).
    for (int i = tid; i < 4096; i += 256) {
        int j = i >> 6, k = i & 63;
        sWl[k * PW + j] = __ldg(&Wl[i]);
        sWr[k * PW + j] = __ldg(&Wr[i]);
    }
    __syncthreads();

    const int nt = tid & 31;
    const int jt = tid >> 5;
    const int n0 = nt * 4;
    const int j0 = jt * 8;

    u64 acc[4][4];
#pragma unroll
    for (int a = 0; a < 4; a++)
#pragma unroll
        for (int b = 0; b < 4; b++) acc[a][b] = 0ULL;

#pragma unroll 4
    for (int k = 0; k < 64; ++k) {
        const float4 am = *reinterpret_cast<const float4*>(&sA[k * PA + n0]);
        const float4 ax = *reinterpret_cast<const float4*>(&sX[k * PA + n0]);
        const ulonglong2* wlp = reinterpret_cast<const ulonglong2*>(&sWl[k * PW + j0]);
        const ulonglong2* wrp = reinterpret_cast<const ulonglong2*>(&sWr[k * PW + j0]);
        const ulonglong2 wlA = wlp[0], wlB = wlp[1];
        const ulonglong2 wrA = wrp[0], wrB = wrp[1];

        u64 da[4], dx[4];
        DUP2(da[0], am.x); DUP2(da[1], am.y); DUP2(da[2], am.z); DUP2(da[3], am.w);
        DUP2(dx[0], ax.x); DUP2(dx[1], ax.y); DUP2(dx[2], ax.z); DUP2(dx[3], ax.w);

#pragma unroll
        for (int ni = 0; ni < 4; ni++) {
            FMA2(acc[ni][0], da[ni], wlA.x, acc[ni][0]);
            FMA2(acc[ni][1], da[ni], wlA.y, acc[ni][1]);
            FMA2(acc[ni][2], da[ni], wlB.x, acc[ni][2]);
            FMA2(acc[ni][3], da[ni], wlB.y, acc[ni][3]);
        }
#pragma unroll
        for (int ni = 0; ni < 4; ni++) {
            FMA2(acc[ni][0], dx[ni], wrA.x, acc[ni][0]);
            FMA2(acc[ni][1], dx[ni], wrA.y, acc[ni][1]);
            FMA2(acc[ni][2], dx[ni], wrB.x, acc[ni][2]);
            FMA2(acc[ni][3], dx[ni], wrB.y, acc[ni][3]);
        }
    }

    float bv[8];
    {
        const float4 b0 = __ldg(reinterpret_cast<const float4*>(&bl[j0]));
        const float4 b1 = __ldg(reinterpret_cast<const float4*>(&bl[j0 + 4]));
        bv[0] = b0.x; bv[1] = b0.y; bv[2] = b0.z; bv[3] = b0.w;
        bv[4] = b1.x; bv[5] = b1.y; bv[6] = b1.z; bv[7] = b1.w;
    }

    float res[4][8];
#pragma unroll
    for (int ni = 0; ni < 4; ni++) {
#pragma unroll
        for (int jp = 0; jp < 4; jp++) {
            unsigned lo, hi;
            UNPK2(lo, hi, acc[ni][jp]);
            res[ni][2 * jp]     = __uint_as_float(lo) + bv[2 * jp];
            res[ni][2 * jp + 1] = __uint_as_float(hi) + bv[2 * jp + 1];
        }
    }

    if (!do_pool) {
#pragma unroll
        for (int ni = 0; ni < 4; ni++) {
            int node = base + n0 + ni;
            if (node < N) {
                uint4 pk;
                pk.x = pack_h2(fmaxf(res[ni][0], 0.f), fmaxf(res[ni][1], 0.f));
                pk.y = pack_h2(fmaxf(res[ni][2], 0.f), fmaxf(res[ni][3], 0.f));
                pk.z = pack_h2(fmaxf(res[ni][4], 0.f), fmaxf(res[ni][5], 0.f));
                pk.w = pack_h2(fmaxf(res[ni][6], 0.f), fmaxf(res[ni][7], 0.f));
                *reinterpret_cast<uint4*>(&hout16[(size_t)node * 64 + j0]) = pk;
            }
        }
    } else {
        __syncthreads();  // done reading sA/sX; reuse as [n][j] pool buffer
        float* pb = sm;   // 128*PW floats < 2*64*PA
#pragma unroll
        for (int ni = 0; ni < 4; ni++) {
            int n = n0 + ni;
            int node = base + n;
            float4 v0, v1;
            if (node < N) {
                v0.x = res[ni][0]; v0.y = res[ni][1]; v0.z = res[ni][2]; v0.w = res[ni][3];
                v1.x = res[ni][4]; v1.y = res[ni][5]; v1.z = res[ni][6]; v1.w = res[ni][7];
            } else {
                v0 = make_float4(0.f, 0.f, 0.f, 0.f);
                v1 = v0;
            }
            float4* p = reinterpret_cast<float4*>(&pb[n * PW + j0]);
            p[0] = v0; p[1] = v1;
        }
        __syncthreads();
        if (tid < 64) {
            const int j = tid;
            int cur = sBat[0];
            float sum = 0.f;
#pragma unroll 4
            for (int n = 0; n < BN; n++) {
                int b = sBat[n];
                if (b != cur) {
                    atomicAdd(&pool_out[cur * 64 + j], sum * sRbc[cur]);
                    sum = 0.f;
                    cur = b;
                }
                sum += pb[n * PW + j];
            }
            atomicAdd(&pool_out[cur * 64 + j], sum * sRbc[cur]);
        }
    }
}

// ---------------------------------------------------------------------------
// kernel_launch
// Inputs: x, edge_index, edge_attr, batch, edge_emb,
//         W1_l, b1_l, W1_r, W2_l, b2_l, W2_r
// ---------------------------------------------------------------------------
extern "C" void kernel_launch(void* const* d_in, const int* in_sizes, int n_in,
                              void* d_out, int out_size) {
    const float* x     = (const float*)d_in[0];
    const int*   eidx  = (const int*)d_in[1];
    const int*   batch = (const int*)d_in[3];
    const float* W1l   = (const float*)d_in[5];
    const float* b1l   = (const float*)d_in[6];
    const float* W1r   = (const float*)d_in[7];
    const float* W2l   = (const float*)d_in[8];
    const float* b2l   = (const float*)d_in[9];
    const float* W2r   = (const float*)d_in[10];
    float*       out   = (float*)d_out;

    const int N = in_sizes[3];
    const int E = in_sizes[1] / 2;
    const int* src = eidx;
    const int* dst = eidx + E;

    void* xp = nullptr; void* hp = nullptr;
    cudaGetSymbolAddress(&xp, g_x16);
    cudaGetSymbolAddress(&hp, g_h16);
    __half* x16 = (__half*)xp;
    __half* h16 = (__half*)hp;

    const int smem = (2 * 64 * PA + 2 * 64 * PW + BN + 64) * (int)sizeof(float)
                     + BN * (int)sizeof(int);
    cudaFuncSetAttribute(sage_kernel, cudaFuncAttributeMaxDynamicSharedMemorySize, smem);

    const int nchunk = (N + CHUNK - 1) / CHUNK;
    const int n_pad  = nchunk * CHUNK;
    const int n4     = N * 16;                       // N*64 floats as float4
    const int zb     = (n4 + 255) / 256;             // covers conversion too
    const int eblk   = (E + 255) / 256;
    const int ablk   = (N + 31) / 32;
    const int gblk   = (N + BN - 1) / BN;

    // CSR build + x conversion (once; reused by both layers)
    zero_kernel<<<zb, 256>>>(n_pad, out, out_size, batch, N,
                             reinterpret_cast<const float4*>(x), n4);
    hist_kernel<<<eblk, 256>>>(dst, E);
    scan_chunk_kernel<<<nchunk, 256>>>();
    add_base_kernel<<<(n_pad + 255) / 256, 256>>>(n_pad);
    fill_kernel<<<eblk, 256>>>(src, dst, E);

    // Layer 1
    agg_kernel<<<ablk, 256>>>(x16, N);
    sage_kernel<<<gblk, 256, smem>>>(x16, W1l, b1l, W1r, h16, nullptr, nullptr, N, 0);

    // Layer 2 + fused scaled pool
    agg_kernel<<<ablk, 256>>>(h16, N);
    sage_kernel<<<gblk, 256, smem>>>(h16, W2l, b2l, W2r, nullptr, batch, out, N, 1);
}

// round 7
// speedup vs baseline: 2.3601x; 1.6094x over previous
#include <cuda_runtime.h>
#include <cuda_fp16.h>

#define D        64
#define MAXN     100352           // padded to multiple of 1024 (scan chunks)
#define MAXE     1000000
#define CHUNK    1024
#define BN       128              // nodes per sage block
#define PAH      136              // smem pitch for fp16 A'/W' tiles (halves): 272B rows
#define PB       68               // pool staging pitch (floats)

static __device__ __forceinline__ unsigned pack_h2(float a, float b) {
    __half2 h = __floats2half2_rn(a, b);
    return *reinterpret_cast<unsigned*>(&h);
}

static __device__ __forceinline__ void ldsm4(unsigned* r, unsigned addr) {
    asm volatile("ldmatrix.sync.aligned.m8n8.x4.shared.b16 {%0,%1,%2,%3}, [%4];"
                 : "=r"(r[0]), "=r"(r[1]), "=r"(r[2]), "=r"(r[3]) : "r"(addr));
}
static __device__ __forceinline__ void mma16816(float* c, const unsigned* a,
                                                unsigned b0, unsigned b1) {
    asm volatile("mma.sync.aligned.m16n8k16.row.col.f32.f16.f16.f32 "
                 "{%0,%1,%2,%3}, {%4,%5,%6,%7}, {%8,%9}, {%0,%1,%2,%3};"
                 : "+f"(c[0]), "+f"(c[1]), "+f"(c[2]), "+f"(c[3])
                 : "r"(a[0]), "r"(a[1]), "r"(a[2]), "r"(a[3]), "r"(b0), "r"(b1));
}

// Static device scratch.
__device__ __half g_mean16[(size_t)MAXN * D];  // pre-scaled mean (fp16)
__device__ __half g_x16[(size_t)MAXN * D];
__device__ __half g_h16[(size_t)MAXN * D];
__device__ int    g_cnt[MAXN];
__device__ int    g_off[MAXN];
__device__ int    g_srcs[MAXE];
__device__ int    g_chunksum[128];
__device__ int    g_chunkbase[128];
__device__ int    g_done;
__device__ float  g_rbc[64];       // 1/max(count(batch==b),1)

// ---------------------------------------------------------------------------
// k0: zero histogram/flags/pool output, convert x -> fp16, per-graph 1/counts.
// ---------------------------------------------------------------------------
__global__ __launch_bounds__(256) void zero_kernel(int n_pad, float* __restrict__ out,
                                                   int n_out, const int* __restrict__ batch,
                                                   int N, const float4* __restrict__ x4,
                                                   int n4) {
    int i = blockIdx.x * 256 + threadIdx.x;
    if (i < n_pad) g_cnt[i] = 0;
    if (i < n_out) out[i] = 0.f;
    if (i == 0) g_done = 0;
    if (i < n4) {
        float4 v = __ldg(&x4[i]);
        uint2 p;
        p.x = pack_h2(v.x, v.y);
        p.y = pack_h2(v.z, v.w);
        reinterpret_cast<uint2*>(g_x16)[i] = p;
    }
    if (blockIdx.x == 0 && threadIdx.x < 64) {
        int b = threadIdx.x;
        int lo0 = 0, hi = N;
        while (lo0 < hi) { int mid = (lo0 + hi) >> 1; if (__ldg(&batch[mid]) < b) lo0 = mid + 1; else hi = mid; }
        int lo1 = lo0; hi = N;
        while (lo1 < hi) { int mid = (lo1 + hi) >> 1; if (__ldg(&batch[mid]) < b + 1) lo1 = mid + 1; else hi = mid; }
        g_rbc[b] = 1.0f / fmaxf((float)(lo1 - lo0), 1.0f);
    }
}

// ---------------------------------------------------------------------------
// k1: in-degree histogram over dst.
// ---------------------------------------------------------------------------
__global__ __launch_bounds__(256) void hist_kernel(const int* __restrict__ dst, int E) {
    int e = blockIdx.x * 256 + threadIdx.x;
    if (e < E) atomicAdd(&g_cnt[__ldg(&dst[e])], 1);
}

// ---------------------------------------------------------------------------
// k2: per-chunk (1024) exclusive scan of g_cnt -> g_off (chunk-local); last
// block scans the chunk totals into g_chunkbase (decoupled via g_done).
// ---------------------------------------------------------------------------
__global__ __launch_bounds__(256) void scan_chunk_kernel() {
    __shared__ int w[256];
    __shared__ int isLast;
    int t = threadIdx.x;
    int base = blockIdx.x * CHUNK + t * 4;
    int4 c = *reinterpret_cast<const int4*>(&g_cnt[base]);
    int s0 = c.x, s1 = s0 + c.y, s2 = s1 + c.z, s3 = s2 + c.w;
    w[t] = s3;
    __syncthreads();
#pragma unroll
    for (int off = 1; off < 256; off <<= 1) {
        int v = (t >= off) ? w[t - off] : 0;
        __syncthreads();
        w[t] += v;
        __syncthreads();
    }
    int excl = (t > 0) ? w[t - 1] : 0;
    int4 o;
    o.x = excl; o.y = excl + s0; o.z = excl + s1; o.w = excl + s2;
    *reinterpret_cast<int4*>(&g_off[base]) = o;
    if (t == 255) g_chunksum[blockIdx.x] = w[255];

    __threadfence();
    if (t == 0) isLast = (atomicAdd(&g_done, 1) == (int)gridDim.x - 1);
    __syncthreads();
    if (isLast) {
        int v = 0;
        if (t < 128 && t < (int)gridDim.x)
            v = *((volatile int*)&g_chunksum[t]);
        if (t < 128) w[t] = v;
        __syncthreads();
#pragma unroll
        for (int off = 1; off < 128; off <<= 1) {
            int u = 0;
            if (t < 128 && t >= off) u = w[t - off];
            __syncthreads();
            if (t < 128) w[t] += u;
            __syncthreads();
        }
        if (t < 128) g_chunkbase[t] = (t > 0) ? w[t - 1] : 0;
    }
}

// ---------------------------------------------------------------------------
// k3: fill dst-sorted src list (adds chunk base on the fly; g_off stays
// chunk-local and becomes chunk-local END offsets).
// ---------------------------------------------------------------------------
__global__ __launch_bounds__(256) void fill_kernel(const int* __restrict__ src,
                                                   const int* __restrict__ dst, int E) {
    int e = blockIdx.x * 256 + threadIdx.x;
    if (e >= E) return;
    int d = __ldg(&dst[e]);
    int p = atomicAdd(&g_off[d], 1) + __ldg(&g_chunkbase[d >> 10]);
    g_srcs[p] = __ldg(&src[e]);
}

// ---------------------------------------------------------------------------
// Gather aggregation (fp16 payload): 8 threads per dst node, shuffle-broadcast
// edge indices, fp32 accumulation, writes PRE-SCALED fp16 mean.
// ---------------------------------------------------------------------------
__global__ __launch_bounds__(256) void agg_kernel(const __half* __restrict__ feat, int N) {
    int g = blockIdx.x * 32 + (threadIdx.x >> 3);
    int lane = threadIdx.x & 7;
    unsigned gmask = 0xFFu << ((threadIdx.x & 31) & ~7);
    bool active = (g < N);
    int cnt = active ? g_cnt[g] : 0;
    int start = active ? (g_off[g] + __ldg(&g_chunkbase[g >> 10]) - cnt) : 0;
    const uint4* f4 = reinterpret_cast<const uint4*>(feat);   // row = 8 uint4
    float a[8];
#pragma unroll
    for (int c = 0; c < 8; c++) a[c] = 0.f;

    for (int i = 0; i < cnt; i += 8) {
        int my = (i + lane < cnt) ? __ldg(&g_srcs[start + i + lane]) : 0;
        int lim = cnt - i;
#pragma unroll
        for (int e = 0; e < 8; e++) {
            if (e >= lim) break;
            int s = __shfl_sync(gmask, my, e, 8);
            uint4 v = __ldg(f4 + (size_t)s * 8 + lane);
            float2 f0 = __half22float2(*reinterpret_cast<__half2*>(&v.x));
            float2 f1 = __half22float2(*reinterpret_cast<__half2*>(&v.y));
            float2 f2 = __half22float2(*reinterpret_cast<__half2*>(&v.z));
            float2 f3 = __half22float2(*reinterpret_cast<__half2*>(&v.w));
            a[0] += f0.x; a[1] += f0.y; a[2] += f1.x; a[3] += f1.y;
            a[4] += f2.x; a[5] += f2.y; a[6] += f3.x; a[7] += f3.y;
        }
    }
    if (active) {
        float r = 1.0f / fmaxf((float)cnt, 1.0f);
        uint4 pk;
        pk.x = pack_h2(a[0] * r, a[1] * r);
        pk.y = pack_h2(a[2] * r, a[3] * r);
        pk.z = pack_h2(a[4] * r, a[5] * r);
        pk.w = pack_h2(a[6] * r, a[7] * r);
        reinterpret_cast<uint4*>(g_mean16)[(size_t)g * 8 + lane] = pk;
    }
}

// ---------------------------------------------------------------------------
// Tensor-core SAGE layer: out = act( [mean|x] @ [Wl|Wr]^T + b )
// 128 nodes/block, 8 warps; warp w owns node rows [w*16, w*16+16), all 64 j.
// mma.sync.m16n8k16 f16 inputs / f32 accum. W is n-major in smem (j rows,
// k contiguous) == exactly the col-major B fragment via NON-trans ldmatrix.
//   do_pool=0 : relu -> hout16 ; do_pool=1 : scaled segmented pool -> pool_out
// ---------------------------------------------------------------------------
__global__ __launch_bounds__(256) void sage_kernel(const __half* __restrict__ xin16,
                                                   const float* __restrict__ Wl,
                                                   const float* __restrict__ bl,
                                                   const float* __restrict__ Wr,
                                                   __half* __restrict__ hout16,
                                                   const int* __restrict__ batch,
                                                   float* __restrict__ pool_out,
                                                   int N, int do_pool) {
    extern __shared__ char smraw[];
    __half* sA   = reinterpret_cast<__half*>(smraw);                 // 128 x PAH halves
    __half* sW   = sA + 128 * PAH;                                   // 64 x PAH halves
    float*  sRbc = reinterpret_cast<float*>(sW + 64 * PAH);          // 64
    int*    sBat = reinterpret_cast<int*>(sRbc + 64);                // 128
    float*  pb   = reinterpret_cast<float*>(smraw);                  // pool reuse: 128 x PB

    const int tid  = threadIdx.x;
    const int base = blockIdx.x * BN;

    if (do_pool) {
        if (tid < BN) {
            int node = base + tid;
            sBat[tid] = (node < N) ? __ldg(&batch[node]) : 0;
        }
        if (tid >= BN && tid < BN + 64) sRbc[tid - BN] = g_rbc[tid - BN];
    }

    // Stage A' = [mean16 | x16] : i -> node n = i>>3, 16B group q = i&7.
    const uint4* m4 = reinterpret_cast<const uint4*>(g_mean16);
    const uint4* x4 = reinterpret_cast<const uint4*>(xin16);
    const uint4 z4 = make_uint4(0u, 0u, 0u, 0u);
    for (int i = tid; i < 2 * BN * 8; i += 256) {
        int half2nd = (i >= BN * 8);
        int ii = i - half2nd * BN * 8;
        int n = ii >> 3, q = ii & 7;
        int node = base + n;
        uint4 v = z4;
        if (node < N)
            v = half2nd ? __ldg(&x4[(size_t)node * 8 + q])
                        : __ldg(&m4[(size_t)node * 8 + q]);
        *reinterpret_cast<uint4*>(&sA[n * PAH + half2nd * 64 + q * 8]) = v;
    }
    // Stage W' = [Wl | Wr] rows j, converted to fp16.
    for (int i = tid; i < 2048; i += 256) {
        int half2nd = (i >= 1024);
        int ii = i - half2nd * 1024;
        int j = ii >> 4, kq = ii & 15;
        float4 v = half2nd ? __ldg(reinterpret_cast<const float4*>(&Wr[j * 64 + kq * 4]))
                           : __ldg(reinterpret_cast<const float4*>(&Wl[j * 64 + kq * 4]));
        uint2 p;
        p.x = pack_h2(v.x, v.y);
        p.y = pack_h2(v.z, v.w);
        *reinterpret_cast<uint2*>(&sW[j * PAH + half2nd * 64 + kq * 4]) = p;
    }
    __syncthreads();

    const int l  = tid & 31;
    const int w  = tid >> 5;
    const int m0 = w * 16;

    unsigned sAb = (unsigned)__cvta_generic_to_shared(sA);
    unsigned sWb = (unsigned)__cvta_generic_to_shared(sW);
    // A frag (x4): lanes 0-7 rows m0+0..7 k0-7 | 8-15 rows m0+8..15 k0-7 |
    //              16-23 rows m0+0..7 k8-15    | 24-31 rows m0+8..15 k8-15
    unsigned aAddr = sAb + (unsigned)((m0 + (l & 15)) * (PAH * 2) + (l >> 4) * 16);
    // B frag (x4, non-trans): lanes 0-7 j0-7 k0-7 | 8-15 j0-7 k8-15 |
    //                         16-23 j8-15 k0-7    | 24-31 j8-15 k8-15
    unsigned bAddr = sWb + (unsigned)((((l & 7) + ((l >> 4) << 3)) * (PAH * 2)) + ((l >> 3) & 1) * 16);

    float acc[8][4];
#pragma unroll
    for (int nt = 0; nt < 8; nt++)
#pragma unroll
        for (int c = 0; c < 4; c++) acc[nt][c] = 0.f;

#pragma unroll
    for (int ks = 0; ks < 8; ks++) {
        unsigned a[4];
        ldsm4(a, aAddr + ks * 32);
#pragma unroll
        for (int np = 0; np < 4; np++) {
            unsigned t[4];
            ldsm4(t, bAddr + np * (16 * PAH * 2) + ks * 32);
            mma16816(acc[2 * np],     a, t[0], t[1]);
            mma16816(acc[2 * np + 1], a, t[2], t[3]);
        }
    }

    // Accumulator mapping: c0,c1 -> row m0+(l>>2), cols nt*8+(l&3)*2,+1 ; c2,c3 -> row+8.
    const int c2 = (l & 3) * 2;
    const int r0 = m0 + (l >> 2);
    const int r1 = r0 + 8;

    if (!do_pool) {
#pragma unroll
        for (int nt = 0; nt < 8; nt++) {
            int col = nt * 8 + c2;
            float b0 = __ldg(&bl[col]), b1 = __ldg(&bl[col + 1]);
            int node0 = base + r0;
            int node1 = base + r1;
            if (node0 < N) {
                unsigned p = pack_h2(fmaxf(acc[nt][0] + b0, 0.f),
                                     fmaxf(acc[nt][1] + b1, 0.f));
                *reinterpret_cast<unsigned*>(&hout16[(size_t)node0 * 64 + col]) = p;
            }
            if (node1 < N) {
                unsigned p = pack_h2(fmaxf(acc[nt][2] + b0, 0.f),
                                     fmaxf(acc[nt][3] + b1, 0.f));
                *reinterpret_cast<unsigned*>(&hout16[(size_t)node1 * 64 + col]) = p;
            }
        }
    } else {
        __syncthreads();  // done with sA region; reuse as pool buffer
#pragma unroll
        for (int nt = 0; nt < 8; nt++) {
            int col = nt * 8 + c2;
            float b0 = __ldg(&bl[col]), b1 = __ldg(&bl[col + 1]);
            float2 v0, v1;
            v0.x = (base + r0 < N) ? acc[nt][0] + b0 : 0.f;
            v0.y = (base + r0 < N) ? acc[nt][1] + b1 : 0.f;
            v1.x = (base + r1 < N) ? acc[nt][2] + b0 : 0.f;
            v1.y = (base + r1 < N) ? acc[nt][3] + b1 : 0.f;
            *reinterpret_cast<float2*>(&pb[r0 * PB + col]) = v0;
            *reinterpret_cast<float2*>(&pb[r1 * PB + col]) = v1;
        }
        __syncthreads();
        if (tid < 64) {
            const int j = tid;
            int cur = sBat[0];
            float sum = 0.f;
#pragma unroll 4
            for (int n = 0; n < BN; n++) {
                int b = sBat[n];
                if (b != cur) {
                    atomicAdd(&pool_out[cur * 64 + j], sum * sRbc[cur]);
                    sum = 0.f;
                    cur = b;
                }
                sum += pb[n * PB + j];
            }
            atomicAdd(&pool_out[cur * 64 + j], sum * sRbc[cur]);
        }
    }
}

// ---------------------------------------------------------------------------
// kernel_launch
// Inputs: x, edge_index, edge_attr, batch, edge_emb,
//         W1_l, b1_l, W1_r, W2_l, b2_l, W2_r
// ---------------------------------------------------------------------------
extern "C" void kernel_launch(void* const* d_in, const int* in_sizes, int n_in,
                              void* d_out, int out_size) {
    const float* x     = (const float*)d_in[0];
    const int*   eidx  = (const int*)d_in[1];
    const int*   batch = (const int*)d_in[3];
    const float* W1l   = (const float*)d_in[5];
    const float* b1l   = (const float*)d_in[6];
    const float* W1r   = (const float*)d_in[7];
    const float* W2l   = (const float*)d_in[8];
    const float* b2l   = (const float*)d_in[9];
    const float* W2r   = (const float*)d_in[10];
    float*       out   = (float*)d_out;

    const int N = in_sizes[3];
    const int E = in_sizes[1] / 2;
    const int* src = eidx;
    const int* dst = eidx + E;

    void* xp = nullptr; void* hp = nullptr;
    cudaGetSymbolAddress(&xp, g_x16);
    cudaGetSymbolAddress(&hp, g_h16);
    __half* x16 = (__half*)xp;
    __half* h16 = (__half*)hp;

    const int smem = (128 + 64) * PAH * (int)sizeof(__half)
                     + 64 * (int)sizeof(float) + BN * (int)sizeof(int);
    cudaFuncSetAttribute(sage_kernel, cudaFuncAttributeMaxDynamicSharedMemorySize, smem);

    const int nchunk = (N + CHUNK - 1) / CHUNK;
    const int n_pad  = nchunk * CHUNK;
    const int n4     = N * 16;                       // N*64 floats as float4
    const int zb     = (n4 + 255) / 256;             // covers conversion too
    const int eblk   = (E + 255) / 256;
    const int ablk   = (N + 31) / 32;
    const int gblk   = (N + BN - 1) / BN;

    // CSR build + x conversion (once; reused by both layers)
    zero_kernel<<<zb, 256>>>(n_pad, out, out_size, batch, N,
                             reinterpret_cast<const float4*>(x), n4);
    hist_kernel<<<eblk, 256>>>(dst, E);
    scan_chunk_kernel<<<nchunk, 256>>>();
    fill_kernel<<<eblk, 256>>>(src, dst, E);

    // Layer 1
    agg_kernel<<<ablk, 256>>>(x16, N);
    sage_kernel<<<gblk, 256, smem>>>(x16, W1l, b1l, W1r, h16, nullptr, nullptr, N, 0);

    // Layer 2 + fused scaled pool
    agg_kernel<<<ablk, 256>>>(h16, N);
    sage_kernel<<<gblk, 256, smem>>>(h16, W2l, b2l, W2r, nullptr, batch, out, N, 1);
}